// round 4
// baseline (speedup 1.0000x reference)
#include <cuda_runtime.h>
#include <math_constants.h>

#define H 512
#define W 512
#define NB 64
#define HW (H * W)
#define NZ (2 * NB)
#define CPWARP 128          // columns per warp (32 lanes x float4)
#define NSTRIP 4            // 512 / 128
#define RPW 64              // rows per warp
#define WPB 8               // warps per block -> 512 rows per block

// Ping-pong skeleton buffers (134 MB each). Referenced ONLY from device code.
__device__ float g_A[(size_t)NZ * HW];
__device__ float g_B[(size_t)NZ * HW];
// Accumulators:
// [0..63] clp*t | [64..127] clp | [128..191] ts*p | [192..255] ts
// [256..319] p*t | [320..383] p | [384..447] t      (all per-batch)
__device__ float g_acc[448];

#define FINF CUDART_INF_F

struct V6 { float L, a, b, c, d, R; };   // 4 packed cols + left/right extra col

// Load row r: 4 cols at cb (float4), plus halo float2 on lanes 0/31.
__device__ __forceinline__ void ldrow(const float* __restrict__ xp, int r,
                                      int cb, int c0, int lane,
                                      float4& v, float& hl0, float& hl1,
                                      float& hr0, float& hr1) {
    hl0 = hl1 = hr0 = hr1 = FINF;
    if ((unsigned)r < (unsigned)H) {
        v = *(const float4*)(xp + (size_t)r * W + cb);
        if (lane == 0 && c0 > 0) {
            float2 t = *(const float2*)(xp + (size_t)r * W + (c0 - 2));
            hl0 = t.x; hl1 = t.y;
        }
        if (lane == 31 && c0 + CPWARP < W) {
            float2 t = *(const float2*)(xp + (size_t)r * W + (c0 + CPWARP));
            hr0 = t.x; hr1 = t.y;
        }
    } else {
        v = make_float4(FINF, FINF, FINF, FINF);
    }
}

// Horizontal 3-min over packed row (+ L/R extra columns).
__device__ __forceinline__ V6 hmin_row(float4 v, float hl0, float hl1,
                                       float hr0, float hr1, int lane) {
    float xm1 = __shfl_up_sync(0xffffffffu, v.w, 1);
    if (lane == 0) xm1 = hl1;
    float xp4 = __shfl_down_sync(0xffffffffu, v.x, 1);
    if (lane == 31) xp4 = hr0;
    V6 h;
    h.a = fminf(xm1, fminf(v.x, v.y));
    h.b = fminf(v.x, fminf(v.y, v.z));
    h.c = fminf(v.y, fminf(v.z, v.w));
    h.d = fminf(v.z, fminf(v.w, xp4));
    h.L = fminf(hl0, fminf(hl1, v.x));
    h.R = fminf(v.w, fminf(hr0, hr1));
    return h;
}

// Vertical 3-min of hm rows -> min_pool row; -inf outside image.
__device__ __forceinline__ V6 vmin3(const V6& p, const V6& q, const V6& s,
                                    bool rowok, bool ledge, bool redge) {
    V6 m;
    if (!rowok) {
        m.L = m.a = m.b = m.c = m.d = m.R = -FINF;
        return m;
    }
    m.a = fminf(p.a, fminf(q.a, s.a));
    m.b = fminf(p.b, fminf(q.b, s.b));
    m.c = fminf(p.c, fminf(q.c, s.c));
    m.d = fminf(p.d, fminf(q.d, s.d));
    m.L = ledge ? -FINF : fminf(p.L, fminf(q.L, s.L));
    m.R = redge ? -FINF : fminf(p.R, fminf(q.R, s.R));
    return m;
}

// Horizontal 3-max over min_pool row (4 valid outputs).
__device__ __forceinline__ float4 hmax_row(const V6& m, int lane) {
    float mm1 = __shfl_up_sync(0xffffffffu, m.d, 1);
    if (lane == 0) mm1 = m.L;
    float mp4 = __shfl_down_sync(0xffffffffu, m.a, 1);
    if (lane == 31) mp4 = m.R;
    float4 h;
    h.x = fmaxf(mm1, fmaxf(m.a, m.b));
    h.y = fmaxf(m.a, fmaxf(m.b, m.c));
    h.z = fmaxf(m.b, fmaxf(m.c, m.d));
    h.w = fmaxf(m.c, fmaxf(m.d, mp4));
    return h;
}

// ---------------------------------------------------------------------------
// One soft-skeletonize iteration (float4 rolling stencil).
// mode 0: inputs -> g_A;  mode 1: g_A -> g_B;  mode 2: g_B -> g_A
// ---------------------------------------------------------------------------
__global__ void __launch_bounds__(256)
skel_step(int mode, const float* __restrict__ pred,
          const float* __restrict__ target) {
    const int z = blockIdx.y;
    const float* __restrict__ xp;
    float* __restrict__ op;
    if (mode == 0) {
        xp = (z < NB) ? pred + (size_t)z * HW : target + (size_t)(z - NB) * HW;
        op = g_A + (size_t)z * HW;
    } else if (mode == 1) {
        xp = g_A + (size_t)z * HW; op = g_B + (size_t)z * HW;
    } else {
        xp = g_B + (size_t)z * HW; op = g_A + (size_t)z * HW;
    }

    const int lane = threadIdx.x & 31;
    const int warp = threadIdx.x >> 5;
    const int c0 = blockIdx.x * CPWARP;
    const int cb = c0 + lane * 4;
    const bool ledge = (c0 == 0);
    const bool redge = (c0 + CPWARP >= W);
    const int r0 = warp * RPW;

    float4 v; float hl0, hl1, hr0, hr1;
    float4 xq0, xq1;

    ldrow(xp, r0 - 2, cb, c0, lane, v, hl0, hl1, hr0, hr1);
    V6 hm_m2 = hmin_row(v, hl0, hl1, hr0, hr1, lane);
    ldrow(xp, r0 - 1, cb, c0, lane, v, hl0, hl1, hr0, hr1);
    V6 hm_m1 = hmin_row(v, hl0, hl1, hr0, hr1, lane);
    ldrow(xp, r0, cb, c0, lane, xq0, hl0, hl1, hr0, hr1);
    V6 hm_0 = hmin_row(xq0, hl0, hl1, hr0, hr1, lane);
    ldrow(xp, r0 + 1, cb, c0, lane, xq1, hl0, hl1, hr0, hr1);
    V6 hm_p1 = hmin_row(xq1, hl0, hl1, hr0, hr1, lane);

    V6 mp_m1 = vmin3(hm_m2, hm_m1, hm_0, (r0 - 1) >= 0, ledge, redge);
    V6 mp0v  = vmin3(hm_m1, hm_0, hm_p1, true, ledge, redge);
    float4 hx_m1 = hmax_row(mp_m1, lane);
    float4 hx_0  = hmax_row(mp0v, lane);
    float4 mp_0 = make_float4(mp0v.a, mp0v.b, mp0v.c, mp0v.d);

    size_t off = (size_t)r0 * W + cb;
    #pragma unroll 4
    for (int r = r0; r < r0 + RPW; ++r) {
        ldrow(xp, r + 2, cb, c0, lane, v, hl0, hl1, hr0, hr1);
        V6 hm_p2 = hmin_row(v, hl0, hl1, hr0, hr1, lane);
        V6 mp_p1 = vmin3(hm_0, hm_p1, hm_p2, (r + 1) < H, ledge, redge);
        float4 hx_p1 = hmax_row(mp_p1, lane);

        float4 o;
        o.x = fmaxf(xq0.x - fmaxf(fmaxf(hx_m1.x, fmaxf(hx_0.x, hx_p1.x)) - mp_0.x, 0.0f), 0.0f);
        o.y = fmaxf(xq0.y - fmaxf(fmaxf(hx_m1.y, fmaxf(hx_0.y, hx_p1.y)) - mp_0.y, 0.0f), 0.0f);
        o.z = fmaxf(xq0.z - fmaxf(fmaxf(hx_m1.z, fmaxf(hx_0.z, hx_p1.z)) - mp_0.z, 0.0f), 0.0f);
        o.w = fmaxf(xq0.w - fmaxf(fmaxf(hx_m1.w, fmaxf(hx_0.w, hx_p1.w)) - mp_0.w, 0.0f), 0.0f);
        *(float4*)(op + off) = o;

        hx_m1 = hx_0; hx_0 = hx_p1;
        mp_0 = make_float4(mp_p1.a, mp_p1.b, mp_p1.c, mp_p1.d);
        hm_0 = hm_p1; hm_p1 = hm_p2;
        xq0 = xq1; xq1 = v;
        off += W;
    }
}

// ---------------------------------------------------------------------------
// Final iteration fused with all reductions (reads g_A; writes only g_acc).
// ---------------------------------------------------------------------------
__global__ void __launch_bounds__(256)
skel_last(const float* __restrict__ pred, const float* __restrict__ target) {
    const int z = blockIdx.y;
    const float* __restrict__ xp = g_A + (size_t)z * HW;
    const int b = (z < NB) ? z : z - NB;
    const float* __restrict__ pb = pred + (size_t)b * HW;
    const float* __restrict__ tb = target + (size_t)b * HW;

    const int lane = threadIdx.x & 31;
    const int warp = threadIdx.x >> 5;
    const int c0 = blockIdx.x * CPWARP;
    const int cb = c0 + lane * 4;
    const bool ledge = (c0 == 0);
    const bool redge = (c0 + CPWARP >= W);
    const int r0 = warp * RPW;

    float4 v; float hl0, hl1, hr0, hr1;
    float4 xq0, xq1;

    ldrow(xp, r0 - 2, cb, c0, lane, v, hl0, hl1, hr0, hr1);
    V6 hm_m2 = hmin_row(v, hl0, hl1, hr0, hr1, lane);
    ldrow(xp, r0 - 1, cb, c0, lane, v, hl0, hl1, hr0, hr1);
    V6 hm_m1 = hmin_row(v, hl0, hl1, hr0, hr1, lane);
    ldrow(xp, r0, cb, c0, lane, xq0, hl0, hl1, hr0, hr1);
    V6 hm_0 = hmin_row(xq0, hl0, hl1, hr0, hr1, lane);
    ldrow(xp, r0 + 1, cb, c0, lane, xq1, hl0, hl1, hr0, hr1);
    V6 hm_p1 = hmin_row(xq1, hl0, hl1, hr0, hr1, lane);

    V6 mp_m1 = vmin3(hm_m2, hm_m1, hm_0, (r0 - 1) >= 0, ledge, redge);
    V6 mp0v  = vmin3(hm_m1, hm_0, hm_p1, true, ledge, redge);
    float4 hx_m1 = hmax_row(mp_m1, lane);
    float4 hx_0  = hmax_row(mp0v, lane);
    float4 mp_0 = make_float4(mp0v.a, mp0v.b, mp0v.c, mp0v.d);

    float s0 = 0, s1 = 0, s2 = 0, s3 = 0, s4 = 0;

    size_t off = (size_t)r0 * W + cb;
    #pragma unroll 4
    for (int r = r0; r < r0 + RPW; ++r) {
        ldrow(xp, r + 2, cb, c0, lane, v, hl0, hl1, hr0, hr1);
        V6 hm_p2 = hmin_row(v, hl0, hl1, hr0, hr1, lane);
        V6 mp_p1 = vmin3(hm_0, hm_p1, hm_p2, (r + 1) < H, ledge, redge);
        float4 hx_p1 = hmax_row(mp_p1, lane);

        float4 o;
        o.x = fmaxf(xq0.x - fmaxf(fmaxf(hx_m1.x, fmaxf(hx_0.x, hx_p1.x)) - mp_0.x, 0.0f), 0.0f);
        o.y = fmaxf(xq0.y - fmaxf(fmaxf(hx_m1.y, fmaxf(hx_0.y, hx_p1.y)) - mp_0.y, 0.0f), 0.0f);
        o.z = fmaxf(xq0.z - fmaxf(fmaxf(hx_m1.z, fmaxf(hx_0.z, hx_p1.z)) - mp_0.z, 0.0f), 0.0f);
        o.w = fmaxf(xq0.w - fmaxf(fmaxf(hx_m1.w, fmaxf(hx_0.w, hx_p1.w)) - mp_0.w, 0.0f), 0.0f);

        if (z < NB) {   // o = cl_pred; accumulate dice terms too
            float4 tv = *(const float4*)(tb + off);
            float4 pv = *(const float4*)(pb + off);
            s0 += o.x * tv.x + o.y * tv.y + o.z * tv.z + o.w * tv.w;
            s1 += o.x + o.y + o.z + o.w;
            s2 += pv.x * tv.x + pv.y * tv.y + pv.z * tv.z + pv.w * tv.w;
            s3 += pv.x + pv.y + pv.z + pv.w;
            s4 += tv.x + tv.y + tv.z + tv.w;
        } else {        // o = target_skeleton
            float4 pv = *(const float4*)(pb + off);
            s0 += o.x * pv.x + o.y * pv.y + o.z * pv.z + o.w * pv.w;
            s1 += o.x + o.y + o.z + o.w;
        }

        hx_m1 = hx_0; hx_0 = hx_p1;
        mp_0 = make_float4(mp_p1.a, mp_p1.b, mp_p1.c, mp_p1.d);
        hm_0 = hm_p1; hm_p1 = hm_p2;
        xq0 = xq1; xq1 = v;
        off += W;
    }

    #pragma unroll
    for (int o = 16; o; o >>= 1) {
        s0 += __shfl_down_sync(0xffffffffu, s0, o);
        s1 += __shfl_down_sync(0xffffffffu, s1, o);
        s2 += __shfl_down_sync(0xffffffffu, s2, o);
        s3 += __shfl_down_sync(0xffffffffu, s3, o);
        s4 += __shfl_down_sync(0xffffffffu, s4, o);
    }
    __shared__ float sred[WPB][5];
    if (lane == 0) {
        sred[warp][0] = s0; sred[warp][1] = s1; sred[warp][2] = s2;
        sred[warp][3] = s3; sred[warp][4] = s4;
    }
    __syncthreads();
    if (threadIdx.x < 5) {
        float vv = 0;
        #pragma unroll
        for (int w = 0; w < WPB; w++) vv += sred[w][threadIdx.x];
        int q = threadIdx.x;
        if (z < NB) {
            int base = (q == 0) ? 0 : (q == 1) ? 64 : (q == 2) ? 256 : (q == 3) ? 320 : 384;
            atomicAdd(&g_acc[base + b], vv);
        } else if (q < 2) {
            atomicAdd(&g_acc[(q == 0 ? 128 : 192) + b], vv);
        }
    }
}

// ---------------------------------------------------------------------------
__global__ void zero_acc() {
    int i = threadIdx.x;
    if (i < 448) g_acc[i] = 0.0f;
}

__global__ void finalize_kernel(float* __restrict__ out) {
    int b = threadIdx.x;  // 64 threads
    float ifl = (g_acc[b] + 1.0f) / (g_acc[64 + b] + 1.0f);
    float tfl = (g_acc[128 + b] + 1.0f) / (g_acc[192 + b] + 1.0f);
    float it = ifl * tfl;
    float s  = ifl + tfl;
    float pt = g_acc[256 + b];
    float sp = g_acc[320 + b];
    float st = g_acc[384 + b];
    #pragma unroll
    for (int o = 16; o; o >>= 1) {
        it += __shfl_down_sync(0xffffffffu, it, o);
        s  += __shfl_down_sync(0xffffffffu, s,  o);
        pt += __shfl_down_sync(0xffffffffu, pt, o);
        sp += __shfl_down_sync(0xffffffffu, sp, o);
        st += __shfl_down_sync(0xffffffffu, st, o);
    }
    __shared__ float sh[5][2];
    if ((threadIdx.x & 31) == 0) {
        int w = threadIdx.x >> 5;
        sh[0][w] = it; sh[1][w] = s; sh[2][w] = pt; sh[3][w] = sp; sh[4][w] = st;
    }
    __syncthreads();
    if (threadIdx.x == 0) {
        float IT = sh[0][0] + sh[0][1];
        float S  = sh[1][0] + sh[1][1];
        float I  = sh[2][0] + sh[2][1];
        float Sp = sh[3][0] + sh[3][1];
        float St = sh[4][0] + sh[4][1];
        float dice   = 1.0f - (2.0f * I + 1e-6f) / (Sp + St + 1e-6f);
        float cldice = 1.0f - 2.0f * IT / S;
        out[0] = 0.8f * dice + 0.2f * cldice;
    }
}

// ---------------------------------------------------------------------------
extern "C" void kernel_launch(void* const* d_in, const int* in_sizes, int n_in,
                              void* d_out, int out_size) {
    const float* pred   = (const float*)d_in[0];
    const float* target = (const float*)d_in[1];
    float* out = (float*)d_out;

    zero_acc<<<1, 448>>>();

    dim3 blk(256);
    dim3 grd(NSTRIP, NZ);  // 4 x 128

    // iter 1: inputs -> A
    skel_step<<<grd, blk>>>(0, pred, target);
    // iters 2..9: even -> (A->B), odd -> (B->A). After iter 9 state is in A.
    for (int k = 2; k <= 9; k++) {
        skel_step<<<grd, blk>>>((k & 1) ? 2 : 1, pred, target);
    }
    // iter 10 fused with reductions (reads A)
    skel_last<<<grd, blk>>>(pred, target);

    finalize_kernel<<<1, 64>>>(out);
}

// round 5
// speedup vs baseline: 1.2436x; 1.2436x over previous
#include <cuda_runtime.h>
#include <math_constants.h>

#define H 512
#define W 512
#define NB 64
#define HW (H * W)
#define NZ (2 * NB)
#define CPWARP 128          // columns per warp (32 lanes x float4)
#define NSTRIP 4            // 512 / 128
#define RPW 16              // rows per warp
#define WPB 8               // warps per block
#define NRG (H / (WPB * RPW))   // row groups = 4

// Ping-pong skeleton buffers (134 MB each). Referenced ONLY from device code.
__device__ float g_A[(size_t)NZ * HW];
__device__ float g_B[(size_t)NZ * HW];
// Accumulators:
// [0..63] clp*t | [64..127] clp | [128..191] ts*p | [192..255] ts
// [256..319] p*t | [320..383] p | [384..447] t      (all per-batch)
__device__ float g_acc[448];

#define FINF CUDART_INF_F

struct V6 { float L, a, b, c, d, R; };   // 4 packed cols + left/right halo col

// Load row r: float4 at cb; halo float2 into (h0,h1): left pair on lane 0,
// right pair on lane 31 (merged registers — mutually exclusive lanes).
__device__ __forceinline__ void ldrow(const float* __restrict__ xp, int r,
                                      int cb, int c0, int lane,
                                      float4& v, float& h0, float& h1) {
    h0 = h1 = FINF;
    if ((unsigned)r < (unsigned)H) {
        v = *(const float4*)(xp + (size_t)r * W + cb);
        if (lane == 0) {
            if (c0 > 0) {
                float2 t = *(const float2*)(xp + (size_t)r * W + (c0 - 2));
                h0 = t.x; h1 = t.y;
            }
        } else if (lane == 31) {
            if (c0 + CPWARP < W) {
                float2 t = *(const float2*)(xp + (size_t)r * W + (c0 + CPWARP));
                h0 = t.x; h1 = t.y;
            }
        }
    } else {
        v = make_float4(FINF, FINF, FINF, FINF);
    }
}

// Horizontal 3-min over packed row (+ halo). L valid on lane 0, R on lane 31.
__device__ __forceinline__ V6 hmin_row(float4 v, float h0, float h1, int lane) {
    float xm1 = __shfl_up_sync(0xffffffffu, v.w, 1);
    if (lane == 0) xm1 = h1;
    float xp4 = __shfl_down_sync(0xffffffffu, v.x, 1);
    if (lane == 31) xp4 = h0;
    V6 h;
    h.a = fminf(xm1, fminf(v.x, v.y));
    h.b = fminf(v.x, fminf(v.y, v.z));
    h.c = fminf(v.y, fminf(v.z, v.w));
    h.d = fminf(v.z, fminf(v.w, xp4));
    h.L = fminf(h0, fminf(h1, v.x));   // lane 0 only
    h.R = fminf(v.w, fminf(h0, h1));   // lane 31 only
    return h;
}

// Vertical 3-min of hm rows -> min_pool row; -inf outside image.
__device__ __forceinline__ V6 vmin3(const V6& p, const V6& q, const V6& s,
                                    bool rowok, bool ledge, bool redge) {
    V6 m;
    if (!rowok) {
        m.L = m.a = m.b = m.c = m.d = m.R = -FINF;
        return m;
    }
    m.a = fminf(p.a, fminf(q.a, s.a));
    m.b = fminf(p.b, fminf(q.b, s.b));
    m.c = fminf(p.c, fminf(q.c, s.c));
    m.d = fminf(p.d, fminf(q.d, s.d));
    m.L = ledge ? -FINF : fminf(p.L, fminf(q.L, s.L));
    m.R = redge ? -FINF : fminf(p.R, fminf(q.R, s.R));
    return m;
}

// Horizontal 3-max over min_pool row (4 valid outputs).
__device__ __forceinline__ float4 hmax_row(const V6& m, int lane) {
    float mm1 = __shfl_up_sync(0xffffffffu, m.d, 1);
    if (lane == 0) mm1 = m.L;
    float mp4 = __shfl_down_sync(0xffffffffu, m.a, 1);
    if (lane == 31) mp4 = m.R;
    float4 h;
    h.x = fmaxf(mm1, fmaxf(m.a, m.b));
    h.y = fmaxf(m.a, fmaxf(m.b, m.c));
    h.z = fmaxf(m.b, fmaxf(m.c, m.d));
    h.w = fmaxf(m.c, fmaxf(m.d, mp4));
    return h;
}

// ---------------------------------------------------------------------------
// One soft-skeletonize iteration (float4 rolling stencil).
// mode 0: inputs -> g_A;  mode 1: g_A -> g_B;  mode 2: g_B -> g_A
// ---------------------------------------------------------------------------
__global__ void __launch_bounds__(256, 4)
skel_step(int mode, const float* __restrict__ pred,
          const float* __restrict__ target) {
    const int z = blockIdx.y;
    const float* __restrict__ xp;
    float* __restrict__ op;
    if (mode == 0) {
        xp = (z < NB) ? pred + (size_t)z * HW : target + (size_t)(z - NB) * HW;
        op = g_A + (size_t)z * HW;
    } else if (mode == 1) {
        xp = g_A + (size_t)z * HW; op = g_B + (size_t)z * HW;
    } else {
        xp = g_B + (size_t)z * HW; op = g_A + (size_t)z * HW;
    }

    const int lane = threadIdx.x & 31;
    const int warp = threadIdx.x >> 5;
    const int c0 = blockIdx.x * CPWARP;
    const int cb = c0 + lane * 4;
    const bool ledge = (c0 == 0);
    const bool redge = (c0 + CPWARP >= W);
    const int r0 = (blockIdx.z * WPB + warp) * RPW;

    float4 v; float h0, h1;
    float4 xq0, xq1;

    ldrow(xp, r0 - 2, cb, c0, lane, v, h0, h1);
    V6 hm_m2 = hmin_row(v, h0, h1, lane);
    ldrow(xp, r0 - 1, cb, c0, lane, v, h0, h1);
    V6 hm_m1 = hmin_row(v, h0, h1, lane);
    ldrow(xp, r0, cb, c0, lane, xq0, h0, h1);
    V6 hm_0 = hmin_row(xq0, h0, h1, lane);
    ldrow(xp, r0 + 1, cb, c0, lane, xq1, h0, h1);
    V6 hm_p1 = hmin_row(xq1, h0, h1, lane);

    V6 mp_m1 = vmin3(hm_m2, hm_m1, hm_0, (r0 - 1) >= 0, ledge, redge);
    V6 mp0v  = vmin3(hm_m1, hm_0, hm_p1, true, ledge, redge);
    float4 hx_m1 = hmax_row(mp_m1, lane);
    float4 hx_0  = hmax_row(mp0v, lane);
    float4 mp_0 = make_float4(mp0v.a, mp0v.b, mp0v.c, mp0v.d);

    size_t off = (size_t)r0 * W + cb;
    #pragma unroll 4
    for (int r = r0; r < r0 + RPW; ++r) {
        ldrow(xp, r + 2, cb, c0, lane, v, h0, h1);
        V6 hm_p2 = hmin_row(v, h0, h1, lane);
        V6 mp_p1 = vmin3(hm_0, hm_p1, hm_p2, (r + 1) < H, ledge, redge);
        float4 hx_p1 = hmax_row(mp_p1, lane);

        float4 o;
        o.x = fmaxf(xq0.x - fmaxf(fmaxf(hx_m1.x, fmaxf(hx_0.x, hx_p1.x)) - mp_0.x, 0.0f), 0.0f);
        o.y = fmaxf(xq0.y - fmaxf(fmaxf(hx_m1.y, fmaxf(hx_0.y, hx_p1.y)) - mp_0.y, 0.0f), 0.0f);
        o.z = fmaxf(xq0.z - fmaxf(fmaxf(hx_m1.z, fmaxf(hx_0.z, hx_p1.z)) - mp_0.z, 0.0f), 0.0f);
        o.w = fmaxf(xq0.w - fmaxf(fmaxf(hx_m1.w, fmaxf(hx_0.w, hx_p1.w)) - mp_0.w, 0.0f), 0.0f);
        *(float4*)(op + off) = o;

        hx_m1 = hx_0; hx_0 = hx_p1;
        mp_0 = make_float4(mp_p1.a, mp_p1.b, mp_p1.c, mp_p1.d);
        hm_0 = hm_p1; hm_p1 = hm_p2;
        xq0 = xq1; xq1 = v;
        off += W;
    }
}

// ---------------------------------------------------------------------------
// Final iteration fused with all reductions (reads g_A; writes only g_acc).
// ---------------------------------------------------------------------------
__global__ void __launch_bounds__(256, 4)
skel_last(const float* __restrict__ pred, const float* __restrict__ target) {
    const int z = blockIdx.y;
    const float* __restrict__ xp = g_A + (size_t)z * HW;
    const int b = (z < NB) ? z : z - NB;
    const float* __restrict__ pb = pred + (size_t)b * HW;
    const float* __restrict__ tb = target + (size_t)b * HW;

    const int lane = threadIdx.x & 31;
    const int warp = threadIdx.x >> 5;
    const int c0 = blockIdx.x * CPWARP;
    const int cb = c0 + lane * 4;
    const bool ledge = (c0 == 0);
    const bool redge = (c0 + CPWARP >= W);
    const int r0 = (blockIdx.z * WPB + warp) * RPW;

    float4 v; float h0, h1;
    float4 xq0, xq1;

    ldrow(xp, r0 - 2, cb, c0, lane, v, h0, h1);
    V6 hm_m2 = hmin_row(v, h0, h1, lane);
    ldrow(xp, r0 - 1, cb, c0, lane, v, h0, h1);
    V6 hm_m1 = hmin_row(v, h0, h1, lane);
    ldrow(xp, r0, cb, c0, lane, xq0, h0, h1);
    V6 hm_0 = hmin_row(xq0, h0, h1, lane);
    ldrow(xp, r0 + 1, cb, c0, lane, xq1, h0, h1);
    V6 hm_p1 = hmin_row(xq1, h0, h1, lane);

    V6 mp_m1 = vmin3(hm_m2, hm_m1, hm_0, (r0 - 1) >= 0, ledge, redge);
    V6 mp0v  = vmin3(hm_m1, hm_0, hm_p1, true, ledge, redge);
    float4 hx_m1 = hmax_row(mp_m1, lane);
    float4 hx_0  = hmax_row(mp0v, lane);
    float4 mp_0 = make_float4(mp0v.a, mp0v.b, mp0v.c, mp0v.d);

    float s0 = 0, s1 = 0, s2 = 0, s3 = 0, s4 = 0;

    size_t off = (size_t)r0 * W + cb;
    #pragma unroll 4
    for (int r = r0; r < r0 + RPW; ++r) {
        ldrow(xp, r + 2, cb, c0, lane, v, h0, h1);
        V6 hm_p2 = hmin_row(v, h0, h1, lane);
        V6 mp_p1 = vmin3(hm_0, hm_p1, hm_p2, (r + 1) < H, ledge, redge);
        float4 hx_p1 = hmax_row(mp_p1, lane);

        float4 o;
        o.x = fmaxf(xq0.x - fmaxf(fmaxf(hx_m1.x, fmaxf(hx_0.x, hx_p1.x)) - mp_0.x, 0.0f), 0.0f);
        o.y = fmaxf(xq0.y - fmaxf(fmaxf(hx_m1.y, fmaxf(hx_0.y, hx_p1.y)) - mp_0.y, 0.0f), 0.0f);
        o.z = fmaxf(xq0.z - fmaxf(fmaxf(hx_m1.z, fmaxf(hx_0.z, hx_p1.z)) - mp_0.z, 0.0f), 0.0f);
        o.w = fmaxf(xq0.w - fmaxf(fmaxf(hx_m1.w, fmaxf(hx_0.w, hx_p1.w)) - mp_0.w, 0.0f), 0.0f);

        if (z < NB) {   // o = cl_pred; accumulate dice terms too
            float4 tv = *(const float4*)(tb + off);
            float4 pv = *(const float4*)(pb + off);
            s0 += o.x * tv.x + o.y * tv.y + o.z * tv.z + o.w * tv.w;
            s1 += o.x + o.y + o.z + o.w;
            s2 += pv.x * tv.x + pv.y * tv.y + pv.z * tv.z + pv.w * tv.w;
            s3 += pv.x + pv.y + pv.z + pv.w;
            s4 += tv.x + tv.y + tv.z + tv.w;
        } else {        // o = target_skeleton
            float4 pv = *(const float4*)(pb + off);
            s0 += o.x * pv.x + o.y * pv.y + o.z * pv.z + o.w * pv.w;
            s1 += o.x + o.y + o.z + o.w;
        }

        hx_m1 = hx_0; hx_0 = hx_p1;
        mp_0 = make_float4(mp_p1.a, mp_p1.b, mp_p1.c, mp_p1.d);
        hm_0 = hm_p1; hm_p1 = hm_p2;
        xq0 = xq1; xq1 = v;
        off += W;
    }

    #pragma unroll
    for (int o = 16; o; o >>= 1) {
        s0 += __shfl_down_sync(0xffffffffu, s0, o);
        s1 += __shfl_down_sync(0xffffffffu, s1, o);
        s2 += __shfl_down_sync(0xffffffffu, s2, o);
        s3 += __shfl_down_sync(0xffffffffu, s3, o);
        s4 += __shfl_down_sync(0xffffffffu, s4, o);
    }
    __shared__ float sred[WPB][5];
    if (lane == 0) {
        sred[warp][0] = s0; sred[warp][1] = s1; sred[warp][2] = s2;
        sred[warp][3] = s3; sred[warp][4] = s4;
    }
    __syncthreads();
    if (threadIdx.x < 5) {
        float vv = 0;
        #pragma unroll
        for (int w = 0; w < WPB; w++) vv += sred[w][threadIdx.x];
        int q = threadIdx.x;
        if (z < NB) {
            int base = (q == 0) ? 0 : (q == 1) ? 64 : (q == 2) ? 256 : (q == 3) ? 320 : 384;
            atomicAdd(&g_acc[base + b], vv);
        } else if (q < 2) {
            atomicAdd(&g_acc[(q == 0 ? 128 : 192) + b], vv);
        }
    }
}

// ---------------------------------------------------------------------------
__global__ void zero_acc() {
    int i = threadIdx.x;
    if (i < 448) g_acc[i] = 0.0f;
}

__global__ void finalize_kernel(float* __restrict__ out) {
    int b = threadIdx.x;  // 64 threads
    float ifl = (g_acc[b] + 1.0f) / (g_acc[64 + b] + 1.0f);
    float tfl = (g_acc[128 + b] + 1.0f) / (g_acc[192 + b] + 1.0f);
    float it = ifl * tfl;
    float s  = ifl + tfl;
    float pt = g_acc[256 + b];
    float sp = g_acc[320 + b];
    float st = g_acc[384 + b];
    #pragma unroll
    for (int o = 16; o; o >>= 1) {
        it += __shfl_down_sync(0xffffffffu, it, o);
        s  += __shfl_down_sync(0xffffffffu, s,  o);
        pt += __shfl_down_sync(0xffffffffu, pt, o);
        sp += __shfl_down_sync(0xffffffffu, sp, o);
        st += __shfl_down_sync(0xffffffffu, st, o);
    }
    __shared__ float sh[5][2];
    if ((threadIdx.x & 31) == 0) {
        int w = threadIdx.x >> 5;
        sh[0][w] = it; sh[1][w] = s; sh[2][w] = pt; sh[3][w] = sp; sh[4][w] = st;
    }
    __syncthreads();
    if (threadIdx.x == 0) {
        float IT = sh[0][0] + sh[0][1];
        float S  = sh[1][0] + sh[1][1];
        float I  = sh[2][0] + sh[2][1];
        float Sp = sh[3][0] + sh[3][1];
        float St = sh[4][0] + sh[4][1];
        float dice   = 1.0f - (2.0f * I + 1e-6f) / (Sp + St + 1e-6f);
        float cldice = 1.0f - 2.0f * IT / S;
        out[0] = 0.8f * dice + 0.2f * cldice;
    }
}

// ---------------------------------------------------------------------------
extern "C" void kernel_launch(void* const* d_in, const int* in_sizes, int n_in,
                              void* d_out, int out_size) {
    const float* pred   = (const float*)d_in[0];
    const float* target = (const float*)d_in[1];
    float* out = (float*)d_out;

    zero_acc<<<1, 448>>>();

    dim3 blk(256);
    dim3 grd(NSTRIP, NZ, NRG);  // 4 x 128 x 4 = 2048 blocks

    // iter 1: inputs -> A
    skel_step<<<grd, blk>>>(0, pred, target);
    // iters 2..9: even -> (A->B), odd -> (B->A). After iter 9 state is in A.
    for (int k = 2; k <= 9; k++) {
        skel_step<<<grd, blk>>>((k & 1) ? 2 : 1, pred, target);
    }
    // iter 10 fused with reductions (reads A)
    skel_last<<<grd, blk>>>(pred, target);

    finalize_kernel<<<1, 64>>>(out);
}